// round 2
// baseline (speedup 1.0000x reference)
#include <cuda_runtime.h>
#include <math.h>

#define NLVL   4
#define AANCH  9
#define BATCH  16
#define PART   18432
#define PPI    12
#define NPARTS (BATCH*PPI)   // 192
#define CAP    768
#define NB     1024
#define LOGIT_SCALE 128.0f   // buckets over logit (0, 8)
#define KPRE   300
#define KOUT   10
#define SEL    512

// scratch (static device globals: no allocation)
__device__ float  g_sc[NPARTS*CAP];
__device__ int    g_ix[NPARTS*CAP];
__device__ float4 g_bx[NPARTS*CAP];
__device__ int    g_cnt[NPARTS];

struct Ptrs {
    const float* cls[4];
    const float* box[4];
    const float* anc[4];
};

// ---------------------------------------------------------------------------
// Kernel A: per-part exact top-300 (valid) candidate selection, logit domain.
// sigmoid(x) > 0.5  <=>  x > 0, and sigmoid is monotonic, so all selection
// happens on raw logits; sigmoid is applied only to the <=640 final outputs.
// ---------------------------------------------------------------------------
__global__ __launch_bounds__(256) void kernelA(Ptrs P) {
    const int pid = blockIdx.x;
    const int b  = pid / PPI;
    const int pp = pid % PPI;
    int lvl, partIdx;
    if      (pp < 8)   { lvl = 0; partIdx = pp; }
    else if (pp < 10)  { lvl = 1; partIdx = pp - 8; }
    else if (pp == 10) { lvl = 2; partIdx = 0; }
    else               { lvl = 3; partIdx = 0; }
    const int HW = (lvl==0) ? 16384 : (lvl==1) ? 4096 : (lvl==2) ? 1024 : 256;
    const int N  = AANCH * HW;
    const int j0 = partIdx * PART;
    const int partN = (PART < N - j0) ? PART : (N - j0);

    const float*  cls   = P.cls[lvl] + (size_t)b * N + j0;
    const float*  boxp0 = P.box[lvl];
    const float*  anc   = P.anc[lvl];

    __shared__ int hist[NB];
    __shared__ int chunk[256];
    __shared__ int s_cnt, s_cut;

    for (int i = threadIdx.x; i < NB; i += 256) hist[i] = 0;
    if (threadIdx.x == 0) s_cnt = 0;
    __syncthreads();

    const int n4 = partN >> 2;
    const float4* cls4 = (const float4*)cls;

    // pass 1: histogram of positive logits (conf > 0.5 <=> logit > 0)
    for (int i = threadIdx.x; i < n4; i += 256) {
        float4 v = cls4[i];
        float xs[4] = {v.x, v.y, v.z, v.w};
        #pragma unroll
        for (int c = 0; c < 4; c++) {
            float x = xs[c];
            if (x > 0.0f) {
                int bk = (int)(x * LOGIT_SCALE);
                bk = bk > NB-1 ? NB-1 : bk;
                atomicAdd(&hist[bk], 1);
            }
        }
    }
    __syncthreads();

    // suffix sums over 4-bucket chunks (Hillis-Steele on reversed order)
    {
        int base = threadIdx.x * 4;
        chunk[threadIdx.x] = hist[base] + hist[base+1] + hist[base+2] + hist[base+3];
        __syncthreads();
        for (int off = 1; off < 256; off <<= 1) {
            int v = chunk[threadIdx.x];
            int add = (threadIdx.x + off < 256) ? chunk[threadIdx.x + off] : 0;
            __syncthreads();
            chunk[threadIdx.x] = v + add;
            __syncthreads();
        }
    }

    int curCut = NB;
    int rawTarget = KPRE;
    while (true) {
        if (threadIdx.x == 0) s_cut = 0;
        __syncthreads();
        // newCut = largest bucket c < curCut with suffix(c) >= rawTarget, else 0
        {
            int base = threadIdx.x * 4;
            int cum = (threadIdx.x + 1 < 256) ? chunk[threadIdx.x + 1] : 0;
            for (int k = 3; k >= 0; k--) {
                cum += hist[base + k];
                int c = base + k;
                if (cum >= rawTarget && c < curCut) { atomicMax(&s_cut, c); break; }
            }
        }
        __syncthreads();
        int newCut = s_cut;

        // collect + decode band [newCut, curCut)
        for (int i = threadIdx.x; i < n4; i += 256) {
            float4 v = cls4[i];
            float xs[4] = {v.x, v.y, v.z, v.w};
            #pragma unroll
            for (int c4 = 0; c4 < 4; c4++) {
                float x = xs[c4];
                if (x > 0.0f) {
                    int bk = (int)(x * LOGIT_SCALE);
                    bk = bk > NB-1 ? NB-1 : bk;
                    if (bk >= newCut && bk < curCut) {
                        int j = j0 + i*4 + c4;
                        int a = j / HW;
                        int rem = j - a*HW;
                        const float* bp = boxp0 + ((size_t)(b*AANCH + a) * 4) * HW + rem;
                        float d0 = bp[0], d1 = bp[HW], d2 = bp[2*HW], d3 = bp[3*HW];
                        float4 an = ((const float4*)anc)[j];
                        float w = an.z - an.x, h = an.w - an.y;
                        float cx = an.x + 0.5f*w, cy = an.y + 0.5f*h;
                        d0 = fminf(fmaxf(d0, -2.0f), 2.0f);
                        d1 = fminf(fmaxf(d1, -2.0f), 2.0f);
                        d2 = fminf(fmaxf(d2, -2.0f), 2.0f);
                        d3 = fminf(fmaxf(d3, -2.0f), 2.0f);
                        float px = cx + d0*w, py = cy + d1*h;
                        float pw = w * expf(d2), ph = h * expf(d3);
                        float x1 = fminf(fmaxf(px - 0.5f*pw, 0.0f), 1024.0f);
                        float y1 = fminf(fmaxf(py - 0.5f*ph, 0.0f), 1024.0f);
                        float x2 = fminf(fmaxf(px + 0.5f*pw, 0.0f), 1024.0f);
                        float y2 = fminf(fmaxf(py + 0.5f*ph, 0.0f), 1024.0f);
                        float bw = x2 - x1, bh = y2 - y1;
                        if (bw > 1.0f && bh > 1.0f && bw < 2000.0f && bh < 2000.0f) {
                            int pos = atomicAdd(&s_cnt, 1);
                            if (pos < CAP) {
                                int g = pid*CAP + pos;
                                g_sc[g] = x;
                                g_ix[g] = j;
                                g_bx[g] = make_float4(x1, y1, x2, y2);
                            }
                        }
                    }
                }
            }
        }
        __syncthreads();
        int cnt = s_cnt;
        curCut = newCut;
        if (cnt >= KPRE || curCut == 0) break;
        rawTarget += (KPRE - cnt) + 16;   // valid shortfall -> extend band
        __syncthreads();
    }
    if (threadIdx.x == 0) g_cnt[pid] = (s_cnt < CAP) ? s_cnt : CAP;
}

// ---------------------------------------------------------------------------
// Kernel B: per image-level merge -> top-300 sorted -> NMS -> output.
// Output layout (tuple (out5 f32[16,40,5], valid bool[16,40])):
//   out_size == 3840 -> valid encoded as floats at element offset 3200
//   out_size == 3360 -> valid encoded as raw bytes at byte offset 12800
// ---------------------------------------------------------------------------
__global__ __launch_bounds__(512) void kernelB(float* out, int out_size) {
    const int img = blockIdx.x;
    const int b   = img >> 2;
    const int lvl = img & 3;
    const int partOffA[4] = {0, 8, 10, 11};
    const int partCntA[4] = {8, 2, 1, 1};
    const int p0 = b*PPI + partOffA[lvl];
    const int np = partCntA[lvl];

    const bool validAsFloat = (out_size >= 3840);
    unsigned char* validB = (unsigned char*)out + 3200u * 4u;
    const int slot0 = b*40 + lvl*10;

    // zero this block's output region (d_out is poisoned)
    {
        int base5 = b*200 + lvl*50;
        if (threadIdx.x < 50) out[base5 + threadIdx.x] = 0.0f;
        if (threadIdx.x >= 64 && threadIdx.x < 74) {
            int k = threadIdx.x - 64;
            if (validAsFloat) out[3200 + slot0 + k] = 0.0f;
            else              validB[slot0 + k] = 0;
        }
    }

    __shared__ int hist[NB];
    __shared__ int chunk[512];
    __shared__ int s_cut, s_scnt;
    __shared__ unsigned long long selKey[SEL];
    __shared__ int selRef[SEL];
    __shared__ float sh_x1[KPRE], sh_y1[KPRE], sh_x2[KPRE], sh_y2[KPRE];
    __shared__ float sh_area[KPRE], sh_logit[KPRE];
    __shared__ int sh_keep[KPRE];
    __shared__ int s_nk, s_done;
    __shared__ int s_pc[8];

    for (int i = threadIdx.x; i < NB; i += 512) hist[i] = 0;
    if (threadIdx.x < np) s_pc[threadIdx.x] = g_cnt[p0 + threadIdx.x];
    if (threadIdx.x == 0) { s_scnt = 0; s_nk = 0; s_done = 0; s_cut = 0; }
    __syncthreads();

    // histogram over merged part entries
    for (int k = 0; k < np; k++) {
        int cnt = s_pc[k];
        int base = (p0 + k) * CAP;
        for (int i = threadIdx.x; i < cnt; i += 512) {
            float x = g_sc[base + i];
            int bk = (int)(x * LOGIT_SCALE); bk = bk > NB-1 ? NB-1 : bk;
            atomicAdd(&hist[bk], 1);
        }
    }
    __syncthreads();
    {
        int base = threadIdx.x * 2;
        chunk[threadIdx.x] = hist[base] + hist[base+1];
        __syncthreads();
        for (int off = 1; off < 512; off <<= 1) {
            int v = chunk[threadIdx.x];
            int add = (threadIdx.x + off < 512) ? chunk[threadIdx.x + off] : 0;
            __syncthreads();
            chunk[threadIdx.x] = v + add;
            __syncthreads();
        }
        int cum = (threadIdx.x + 1 < 512) ? chunk[threadIdx.x + 1] : 0;
        for (int k = 1; k >= 0; k--) {
            cum += hist[base + k];
            if (cum >= KPRE) { atomicMax(&s_cut, base + k); break; }
        }
    }
    __syncthreads();
    int cut = s_cut;

    // collect superset of top-300 with 64-bit key (logit bits desc, idx asc)
    for (int k = 0; k < np; k++) {
        int cnt = s_pc[k];
        int base = (p0 + k) * CAP;
        for (int i = threadIdx.x; i < cnt; i += 512) {
            float x = g_sc[base + i];
            int bk = (int)(x * LOGIT_SCALE); bk = bk > NB-1 ? NB-1 : bk;
            if (bk >= cut) {
                int pos = atomicAdd(&s_scnt, 1);
                if (pos < SEL) {
                    unsigned int xb = __float_as_uint(x);
                    unsigned int jj = (unsigned int)g_ix[base + i];
                    selKey[pos] = ((unsigned long long)xb << 32)
                                | (unsigned long long)(0xFFFFFFFFu - jj);
                    selRef[pos] = base + i;
                }
            }
        }
    }
    __syncthreads();
    int scnt = s_scnt < SEL ? s_scnt : SEL;
    for (int i = scnt + threadIdx.x; i < SEL; i += 512) { selKey[i] = 0ull; selRef[i] = -1; }
    __syncthreads();

    // bitonic sort, descending, 512 elements / 512 threads
    for (int k = 2; k <= SEL; k <<= 1) {
        for (int j = k >> 1; j > 0; j >>= 1) {
            int ixj = threadIdx.x ^ j;
            if (ixj > threadIdx.x) {
                bool segDesc = ((threadIdx.x & k) == 0);
                unsigned long long a = selKey[threadIdx.x], c = selKey[ixj];
                bool sw = segDesc ? (a < c) : (a > c);
                if (sw) {
                    selKey[threadIdx.x] = c; selKey[ixj] = a;
                    int t = selRef[threadIdx.x]; selRef[threadIdx.x] = selRef[ixj]; selRef[ixj] = t;
                }
            }
            __syncthreads();
        }
    }

    int m = scnt < KPRE ? scnt : KPRE;
    for (int i = threadIdx.x; i < KPRE; i += 512) {
        if (i < m) {
            float4 bb = g_bx[selRef[i]];
            sh_x1[i] = bb.x; sh_y1[i] = bb.y; sh_x2[i] = bb.z; sh_y2[i] = bb.w;
            sh_area[i] = (bb.z - bb.x) * (bb.w - bb.y);
            sh_logit[i] = __uint_as_float((unsigned int)(selKey[i] >> 32));
            sh_keep[i] = 1;
        } else {
            sh_keep[i] = 0;
            sh_x1[i] = sh_y1[i] = sh_x2[i] = sh_y2[i] = 0.0f;
            sh_area[i] = 0.0f;
        }
    }
    __syncthreads();

    // greedy NMS with early exit after 10 kept (exact: suppressions by the
    // 11th+ kept box can only affect boxes that were never in the first 10)
    for (int i = 0; i < KPRE; i++) {
        if (s_done) break;
        if (sh_keep[i]) {
            if (threadIdx.x == 0) {
                int nk = s_nk;
                float sc = 1.0f / (1.0f + expf(-sh_logit[i]));
                int s5 = b*200 + (lvl*10 + nk)*5;
                out[s5+0] = sh_x1[i]; out[s5+1] = sh_y1[i];
                out[s5+2] = sh_x2[i]; out[s5+3] = sh_y2[i];
                out[s5+4] = sc;
                if (validAsFloat) out[3200 + slot0 + nk] = 1.0f;
                else              validB[slot0 + nk] = 1;
                s_nk = nk + 1;
                if (nk + 1 >= KOUT) s_done = 1;
            }
            float bx1 = sh_x1[i], by1 = sh_y1[i], bx2 = sh_x2[i], by2 = sh_y2[i];
            float ba = sh_area[i];
            for (int jj = i + 1 + threadIdx.x; jj < KPRE; jj += 512) {
                if (sh_keep[jj]) {
                    float ix1 = fmaxf(bx1, sh_x1[jj]);
                    float iy1 = fmaxf(by1, sh_y1[jj]);
                    float ix2 = fminf(bx2, sh_x2[jj]);
                    float iy2 = fminf(by2, sh_y2[jj]);
                    float iw = fmaxf(ix2 - ix1, 0.0f);
                    float ih = fmaxf(iy2 - iy1, 0.0f);
                    float inter = iw * ih;
                    float iou = inter / (ba + sh_area[jj] - inter + 1e-9f);
                    if (iou > 0.3f) sh_keep[jj] = 0;
                }
            }
        }
        __syncthreads();
    }
}

// ---------------------------------------------------------------------------
extern "C" void kernel_launch(void* const* d_in, const int* in_sizes, int n_in,
                              void* d_out, int out_size) {
    Ptrs P;
    // detect input ordering by sizes:
    //  interleaved (setup dict order): cls0,box0,anc0,cls1,...  -> sizes[1] = 9437184
    //  grouped (signature order):      cls0..3,box0..3,anc0..3  -> sizes[0] = 2359296, sizes[1] = 589824
    //  alphabetical:                   anc0..3,box0..3,cls0..3  -> sizes[0] = 589824
    if (n_in >= 2 && in_sizes[0] == 2359296 && in_sizes[1] == 9437184) {
        for (int l = 0; l < 4; l++) {
            P.cls[l] = (const float*)d_in[3*l + 0];
            P.box[l] = (const float*)d_in[3*l + 1];
            P.anc[l] = (const float*)d_in[3*l + 2];
        }
    } else if (n_in >= 1 && in_sizes[0] == 2359296) {
        for (int l = 0; l < 4; l++) {
            P.cls[l] = (const float*)d_in[l];
            P.box[l] = (const float*)d_in[4 + l];
            P.anc[l] = (const float*)d_in[8 + l];
        }
    } else {
        for (int l = 0; l < 4; l++) {
            P.anc[l] = (const float*)d_in[l];
            P.box[l] = (const float*)d_in[4 + l];
            P.cls[l] = (const float*)d_in[8 + l];
        }
    }
    kernelA<<<NPARTS, 256>>>(P);
    kernelB<<<64, 512>>>((float*)d_out, out_size);
}

// round 4
// speedup vs baseline: 1.4607x; 1.4607x over previous
#include <cuda_runtime.h>
#include <math.h>

#define NLVL   4
#define AANCH  9
#define BATCH  16
#define PART   18432
#define PPI    12
#define NPARTS (BATCH*PPI)   // 192
#define CAP    768
#define NB     1024
#define LOGIT_SCALE 128.0f   // buckets over logit (0, 8)
#define KPRE   300
#define KOUT   10
#define SEL    512
#define CACHE_CAP 4096
#define FLOOR_BK  128        // cache floor: logit >= 1.0

// scratch (static device globals: no allocation)
__device__ float  g_sc[NPARTS*CAP];
__device__ int    g_ix[NPARTS*CAP];
__device__ float4 g_bx[NPARTS*CAP];
__device__ int    g_cnt[NPARTS];

struct Ptrs {
    const float* cls[4];
    const float* box[4];
    const float* anc[4];
};

// ---------------------------------------------------------------------------
// Kernel A: per-part exact top-300 (valid) candidate selection, logit domain.
// sigmoid(x) > 0.5  <=>  x > 0; sigmoid is monotonic -> select on raw logits.
// ---------------------------------------------------------------------------
__global__ __launch_bounds__(256) void kernelA(Ptrs P) {
    const int pid = blockIdx.x;
    const int b  = pid / PPI;
    const int pp = pid % PPI;
    int lvl, partIdx;
    if      (pp < 8)   { lvl = 0; partIdx = pp; }
    else if (pp < 10)  { lvl = 1; partIdx = pp - 8; }
    else if (pp == 10) { lvl = 2; partIdx = 0; }
    else               { lvl = 3; partIdx = 0; }
    const int HW = (lvl==0) ? 16384 : (lvl==1) ? 4096 : (lvl==2) ? 1024 : 256;
    const int N  = AANCH * HW;
    const int j0 = partIdx * PART;
    const int partN = (PART < N - j0) ? PART : (N - j0);

    const float*  cls   = P.cls[lvl] + (size_t)b * N + j0;
    const float*  boxp0 = P.box[lvl];
    const float*  anc   = P.anc[lvl];

    __shared__ int   hist[NB];
    __shared__ int   chunk[256];
    __shared__ float cval[CACHE_CAP];
    __shared__ int   cidx[CACHE_CAP];
    __shared__ int   s_cnt, s_ccnt, s_cut;

    const int tid = threadIdx.x;
    for (int i = tid; i < NB; i += 256) hist[i] = 0;
    if (tid == 0) { s_cnt = 0; s_ccnt = 0; }
    __syncthreads();

    const int n4 = partN >> 2;
    const float4* cls4 = (const float4*)cls;

    // pass 1: histogram of positive logits + smem cache of (val,idx) for
    // logit >= 1.0 (bucket >= FLOOR_BK). 4x batched loads for MLP.
    auto proc = [&](float4 v, int i4) {
        float xs[4] = {v.x, v.y, v.z, v.w};
        #pragma unroll
        for (int c = 0; c < 4; c++) {
            float x = xs[c];
            if (x > 0.0f) {
                int bk = (int)(x * LOGIT_SCALE);
                bk = bk > NB-1 ? NB-1 : bk;
                atomicAdd(&hist[bk], 1);
                if (bk >= FLOOR_BK) {
                    int pos = atomicAdd(&s_ccnt, 1);
                    if (pos < CACHE_CAP) { cval[pos] = x; cidx[pos] = i4*4 + c; }
                }
            }
        }
    };
    {
        int i = tid;
        for (; i + 768 < n4; i += 1024) {
            float4 v0 = cls4[i];
            float4 v1 = cls4[i + 256];
            float4 v2 = cls4[i + 512];
            float4 v3 = cls4[i + 768];
            proc(v0, i); proc(v1, i + 256); proc(v2, i + 512); proc(v3, i + 768);
        }
        for (; i < n4; i += 256) proc(cls4[i], i);
    }
    __syncthreads();

    const bool cacheOK = (s_ccnt <= CACHE_CAP);
    const int  ccnt    = s_ccnt < CACHE_CAP ? s_ccnt : CACHE_CAP;

    // suffix sums over 4-bucket chunks (Hillis-Steele on reversed order)
    {
        int base = tid * 4;
        chunk[tid] = hist[base] + hist[base+1] + hist[base+2] + hist[base+3];
        __syncthreads();
        for (int off = 1; off < 256; off <<= 1) {
            int v = chunk[tid];
            int add = (tid + off < 256) ? chunk[tid + off] : 0;
            __syncthreads();
            chunk[tid] = v + add;
            __syncthreads();
        }
    }

    // decode + store helper
    auto decode_store = [&](float x, int jrel) {
        int j = j0 + jrel;
        int a = j / HW;
        int rem = j - a*HW;
        const float* bp = boxp0 + ((size_t)(b*AANCH + a) * 4) * HW + rem;
        float d0 = bp[0], d1 = bp[HW], d2 = bp[2*HW], d3 = bp[3*HW];
        float4 an = ((const float4*)anc)[j];
        float w = an.z - an.x, h = an.w - an.y;
        float cx = an.x + 0.5f*w, cy = an.y + 0.5f*h;
        d0 = fminf(fmaxf(d0, -2.0f), 2.0f);
        d1 = fminf(fmaxf(d1, -2.0f), 2.0f);
        d2 = fminf(fmaxf(d2, -2.0f), 2.0f);
        d3 = fminf(fmaxf(d3, -2.0f), 2.0f);
        float px = cx + d0*w, py = cy + d1*h;
        float pw = w * expf(d2), ph = h * expf(d3);
        float x1 = fminf(fmaxf(px - 0.5f*pw, 0.0f), 1024.0f);
        float y1 = fminf(fmaxf(py - 0.5f*ph, 0.0f), 1024.0f);
        float x2 = fminf(fmaxf(px + 0.5f*pw, 0.0f), 1024.0f);
        float y2 = fminf(fmaxf(py + 0.5f*ph, 0.0f), 1024.0f);
        float bw = x2 - x1, bh = y2 - y1;
        if (bw > 1.0f && bh > 1.0f && bw < 2000.0f && bh < 2000.0f) {
            int pos = atomicAdd(&s_cnt, 1);
            if (pos < CAP) {
                int g = pid*CAP + pos;
                g_sc[g] = x;
                g_ix[g] = j;
                g_bx[g] = make_float4(x1, y1, x2, y2);
            }
        }
    };

    int curCut = NB;
    int rawTarget = KPRE;
    while (true) {
        if (tid == 0) s_cut = 0;
        __syncthreads();
        // newCut = largest bucket c < curCut with suffix(c) >= rawTarget, else 0
        {
            int base = tid * 4;
            int cum = (tid + 1 < 256) ? chunk[tid + 1] : 0;
            for (int k = 3; k >= 0; k--) {
                cum += hist[base + k];
                int c = base + k;
                if (cum >= rawTarget && c < curCut) { atomicMax(&s_cut, c); break; }
            }
        }
        __syncthreads();
        int newCut = s_cut;

        if (cacheOK && newCut >= FLOOR_BK) {
            // collect band [newCut, curCut) from smem cache
            for (int t = tid; t < ccnt; t += 256) {
                float x = cval[t];
                int bk = (int)(x * LOGIT_SCALE);
                bk = bk > NB-1 ? NB-1 : bk;
                if (bk >= newCut && bk < curCut) decode_store(x, cidx[t]);
            }
        } else {
            // fallback: rescan global cls for the band
            for (int i = tid; i < n4; i += 256) {
                float4 v = cls4[i];
                float xs[4] = {v.x, v.y, v.z, v.w};
                #pragma unroll
                for (int c4 = 0; c4 < 4; c4++) {
                    float x = xs[c4];
                    if (x > 0.0f) {
                        int bk = (int)(x * LOGIT_SCALE);
                        bk = bk > NB-1 ? NB-1 : bk;
                        if (bk >= newCut && bk < curCut) decode_store(x, i*4 + c4);
                    }
                }
            }
        }
        __syncthreads();
        int cnt = s_cnt;
        curCut = newCut;
        if (cnt >= KPRE || curCut == 0) break;
        rawTarget += (KPRE - cnt) + 16;   // valid shortfall -> extend band
        __syncthreads();
    }
    if (tid == 0) g_cnt[pid] = (s_cnt < CAP) ? s_cnt : CAP;
}

// ---------------------------------------------------------------------------
// Kernel B: per image-level merge -> top-300 sorted -> NMS -> output.
// Output layout (tuple (out5 f32[16,40,5], valid bool[16,40])):
//   out_size == 3840 -> valid encoded as floats at element offset 3200
//   out_size == 3360 -> valid encoded as raw bytes at byte offset 12800
// ---------------------------------------------------------------------------
__global__ __launch_bounds__(512) void kernelB(float* out, int out_size) {
    const int img = blockIdx.x;
    const int b   = img >> 2;
    const int lvl = img & 3;
    const int partOffA[4] = {0, 8, 10, 11};
    const int partCntA[4] = {8, 2, 1, 1};
    const int p0 = b*PPI + partOffA[lvl];
    const int np = partCntA[lvl];
    const int tid = threadIdx.x;

    const bool validAsFloat = (out_size >= 3840);
    unsigned char* validB = (unsigned char*)out + 3200u * 4u;
    const int slot0 = b*40 + lvl*10;

    // zero this block's output region (d_out is poisoned)
    {
        int base5 = b*200 + lvl*50;
        if (tid < 50) out[base5 + tid] = 0.0f;
        if (tid >= 64 && tid < 74) {
            int k = tid - 64;
            if (validAsFloat) out[3200 + slot0 + k] = 0.0f;
            else              validB[slot0 + k] = 0;
        }
    }

    __shared__ int hist[NB];
    __shared__ int chunk[512];
    __shared__ int s_cut, s_scnt;
    __shared__ unsigned long long sKey[SEL];
    __shared__ int sRef[SEL];
    __shared__ float sh_x1[KPRE], sh_y1[KPRE], sh_x2[KPRE], sh_y2[KPRE];
    __shared__ float sh_area[KPRE], sh_logit[KPRE];
    __shared__ unsigned sh_keepw[(KPRE+31)/32];   // 10 words
    __shared__ int s_next, s_nk;
    __shared__ int s_pc[8];

    for (int i = tid; i < NB; i += 512) hist[i] = 0;
    if (tid < np) s_pc[tid] = g_cnt[p0 + tid];
    if (tid == 0) { s_scnt = 0; s_nk = 0; s_cut = 0; }
    __syncthreads();

    // histogram over merged part entries
    for (int k = 0; k < np; k++) {
        int cnt = s_pc[k];
        int base = (p0 + k) * CAP;
        for (int i = tid; i < cnt; i += 512) {
            float x = g_sc[base + i];
            int bk = (int)(x * LOGIT_SCALE); bk = bk > NB-1 ? NB-1 : bk;
            atomicAdd(&hist[bk], 1);
        }
    }
    __syncthreads();
    {
        int base = tid * 2;
        chunk[tid] = hist[base] + hist[base+1];
        __syncthreads();
        for (int off = 1; off < 512; off <<= 1) {
            int v = chunk[tid];
            int add = (tid + off < 512) ? chunk[tid + off] : 0;
            __syncthreads();
            chunk[tid] = v + add;
            __syncthreads();
        }
        int cum = (tid + 1 < 512) ? chunk[tid + 1] : 0;
        for (int k = 1; k >= 0; k--) {
            cum += hist[base + k];
            if (cum >= KPRE) { atomicMax(&s_cut, base + k); break; }
        }
    }
    __syncthreads();
    int cut = s_cut;

    // collect superset of top-300 with 64-bit key (logit bits desc, idx asc)
    for (int k = 0; k < np; k++) {
        int cnt = s_pc[k];
        int base = (p0 + k) * CAP;
        for (int i = tid; i < cnt; i += 512) {
            float x = g_sc[base + i];
            int bk = (int)(x * LOGIT_SCALE); bk = bk > NB-1 ? NB-1 : bk;
            if (bk >= cut) {
                int pos = atomicAdd(&s_scnt, 1);
                if (pos < SEL) {
                    unsigned int xb = __float_as_uint(x);
                    unsigned int jj = (unsigned int)g_ix[base + i];
                    sKey[pos] = ((unsigned long long)xb << 32)
                              | (unsigned long long)(0xFFFFFFFFu - jj);
                    sRef[pos] = base + i;
                }
            }
        }
    }
    __syncthreads();
    int scnt = s_scnt < SEL ? s_scnt : SEL;
    for (int i = scnt + tid; i < SEL; i += 512) { sKey[i] = 0ull; sRef[i] = -1; }
    __syncthreads();

    // bitonic sort (descending) 512 elems: register-resident; warp-local
    // phases (j<32) via shfl_xor, cross-warp phases via shared + 2 syncs.
    {
        unsigned long long key = sKey[tid];
        int ref = sRef[tid];
        __syncthreads();
        #pragma unroll
        for (int k = 2; k <= SEL; k <<= 1) {
            bool segDesc = ((tid & k) == 0);
            #pragma unroll
            for (int j = k >> 1; j > 0; j >>= 1) {
                unsigned long long okey; int oref;
                if (j >= 32) {
                    sKey[tid] = key; sRef[tid] = ref;
                    __syncthreads();
                    okey = sKey[tid ^ j]; oref = sRef[tid ^ j];
                    __syncthreads();
                } else {
                    okey = __shfl_xor_sync(0xFFFFFFFFu, key, j);
                    oref = __shfl_xor_sync(0xFFFFFFFFu, ref, j);
                }
                bool keepMax = (((tid & j) == 0) == segDesc);
                bool takeOther = keepMax ? (okey > key) : (okey < key);
                if (takeOther) { key = okey; ref = oref; }
            }
        }
        sKey[tid] = key; sRef[tid] = ref;
        __syncthreads();
    }

    const int m = scnt < KPRE ? scnt : KPRE;
    for (int i = tid; i < m; i += 512) {
        float4 bb = g_bx[sRef[i]];
        sh_x1[i] = bb.x; sh_y1[i] = bb.y; sh_x2[i] = bb.z; sh_y2[i] = bb.w;
        sh_area[i] = (bb.z - bb.x) * (bb.w - bb.y);
        sh_logit[i] = __uint_as_float((unsigned int)(sKey[i] >> 32));
    }
    if (tid < (KPRE+31)/32) {
        int lo = tid * 32;
        unsigned w;
        if (m >= lo + 32) w = 0xFFFFFFFFu;
        else if (m > lo)  w = (1u << (m - lo)) - 1u;
        else              w = 0u;
        sh_keepw[tid] = w;
    }
    __syncthreads();

    // greedy NMS, one round per KEPT box (<= 10 rounds): find lowest
    // surviving candidate, emit it, suppress in parallel. Exact: boxes
    // beyond the 10th kept cannot alter the first-10 prefix.
    for (int round = 0; round <= KOUT; round++) {
        if (tid < 32) {
            unsigned v = (tid < 10) ? sh_keepw[tid] : 0u;
            unsigned nz = __ballot_sync(0xFFFFFFFFu, v != 0u);
            int w = __ffs(nz) - 1;
            unsigned vw = __shfl_sync(0xFFFFFFFFu, v, (w < 0) ? 0 : w);
            if (tid == 0) s_next = nz ? (w*32 + __ffs(vw) - 1) : -1;
        }
        __syncthreads();
        int i = s_next;
        if (i < 0 || s_nk >= KOUT) break;

        float bx1 = sh_x1[i], by1 = sh_y1[i], bx2 = sh_x2[i], by2 = sh_y2[i];
        float ba = sh_area[i];

        if (tid == 0) {
            int nk = s_nk;
            float sc = 1.0f / (1.0f + expf(-sh_logit[i]));
            int s5 = b*200 + (lvl*10 + nk)*5;
            out[s5+0] = bx1; out[s5+1] = by1;
            out[s5+2] = bx2; out[s5+3] = by2;
            out[s5+4] = sc;
            if (validAsFloat) out[3200 + slot0 + nk] = 1.0f;
            else              validB[slot0 + nk] = 1;
            s_nk = nk + 1;
            atomicAnd(&sh_keepw[i >> 5], ~(1u << (i & 31)));
        }
        int j = tid;
        if (j > i && j < m && ((sh_keepw[j >> 5] >> (j & 31)) & 1u)) {
            float ix1 = fmaxf(bx1, sh_x1[j]);
            float iy1 = fmaxf(by1, sh_y1[j]);
            float ix2 = fminf(bx2, sh_x2[j]);
            float iy2 = fminf(by2, sh_y2[j]);
            float iw = fmaxf(ix2 - ix1, 0.0f);
            float ih = fmaxf(iy2 - iy1, 0.0f);
            float inter = iw * ih;
            float iou = inter / (ba + sh_area[j] - inter + 1e-9f);
            if (iou > 0.3f) atomicAnd(&sh_keepw[j >> 5], ~(1u << (j & 31)));
        }
        __syncthreads();
    }
}

// ---------------------------------------------------------------------------
extern "C" void kernel_launch(void* const* d_in, const int* in_sizes, int n_in,
                              void* d_out, int out_size) {
    Ptrs P;
    if (n_in >= 2 && in_sizes[0] == 2359296 && in_sizes[1] == 9437184) {
        for (int l = 0; l < 4; l++) {
            P.cls[l] = (const float*)d_in[3*l + 0];
            P.box[l] = (const float*)d_in[3*l + 1];
            P.anc[l] = (const float*)d_in[3*l + 2];
        }
    } else if (n_in >= 1 && in_sizes[0] == 2359296) {
        for (int l = 0; l < 4; l++) {
            P.cls[l] = (const float*)d_in[l];
            P.box[l] = (const float*)d_in[4 + l];
            P.anc[l] = (const float*)d_in[8 + l];
        }
    } else {
        for (int l = 0; l < 4; l++) {
            P.anc[l] = (const float*)d_in[l];
            P.box[l] = (const float*)d_in[4 + l];
            P.cls[l] = (const float*)d_in[8 + l];
        }
    }
    kernelA<<<NPARTS, 256>>>(P);
    kernelB<<<64, 512>>>((float*)d_out, out_size);
}

// round 5
// speedup vs baseline: 1.5981x; 1.0941x over previous
#include <cuda_runtime.h>
#include <math.h>

#define NLVL   4
#define AANCH  9
#define BATCH  16
#define PART   18432
#define PPI    12
#define NPARTS (BATCH*PPI)   // 192
#define CAP    768
#define NB     1024
#define LOGIT_SCALE 128.0f   // buckets over logit (0, 8)
#define KPRE   300
#define KOUT   10
#define SEL    512
#define CACHE_CAP 4096
#define RAW_TARGET0 420      // overshoot so one band pass usually suffices

// scratch (static device globals: no allocation)
__device__ float  g_sc[NPARTS*CAP];
__device__ int    g_ix[NPARTS*CAP];
__device__ float4 g_bx[NPARTS*CAP];
__device__ int    g_cnt[NPARTS];

struct Ptrs {
    const float* cls[4];
    const float* box[4];
    const float* anc[4];
};

// ---------------------------------------------------------------------------
// Kernel A: per-part exact top-k-valid candidate selection, logit domain.
// sigmoid(x) > 0.5  <=>  x > 0; sigmoid monotonic -> select on raw logits.
// ---------------------------------------------------------------------------
__global__ __launch_bounds__(256) void kernelA(Ptrs P) {
    const int pid = blockIdx.x;
    const int b  = pid / PPI;
    const int pp = pid % PPI;
    int lvl, partIdx;
    if      (pp < 8)   { lvl = 0; partIdx = pp; }
    else if (pp < 10)  { lvl = 1; partIdx = pp - 8; }
    else if (pp == 10) { lvl = 2; partIdx = 0; }
    else               { lvl = 3; partIdx = 0; }
    const int HW = (lvl==0) ? 16384 : (lvl==1) ? 4096 : (lvl==2) ? 1024 : 256;
    const int N  = AANCH * HW;
    const int j0 = partIdx * PART;
    const int partN = (PART < N - j0) ? PART : (N - j0);
    // cache floor bucket per level (cache stays within CACHE_CAP w.h.p.;
    // exactness guarded by cacheOK + global-band fallback below)
    const int flBK = (lvl == 3) ? 0 : 128;

    const float*  cls   = P.cls[lvl] + (size_t)b * N + j0;
    const float*  boxp0 = P.box[lvl];
    const float*  anc   = P.anc[lvl];

    __shared__ int   hist[NB];
    __shared__ float cval[CACHE_CAP];
    __shared__ int   cidx[CACHE_CAP];
    __shared__ int   wtot[8];
    __shared__ int   s_cnt, s_ccnt, s_cut;

    const int tid  = threadIdx.x;
    const int wid  = tid >> 5;
    const int lane = tid & 31;

    for (int i = tid; i < NB; i += 256) hist[i] = 0;
    if (tid == 0) { s_cnt = 0; s_ccnt = 0; }
    __syncthreads();

    const int n4 = partN >> 2;
    const float4* cls4 = (const float4*)cls;

    // pass 1: histogram of positive logits + smem cache of (val,idx) above
    // the floor bucket. 6x batched loads for MLP.
    auto proc = [&](float4 v, int i4) {
        float xs[4] = {v.x, v.y, v.z, v.w};
        #pragma unroll
        for (int c = 0; c < 4; c++) {
            float x = xs[c];
            if (x > 0.0f) {
                int bk = (int)(x * LOGIT_SCALE);
                bk = bk > NB-1 ? NB-1 : bk;
                atomicAdd(&hist[bk], 1);
                if (bk >= flBK) {
                    int pos = atomicAdd(&s_ccnt, 1);
                    if (pos < CACHE_CAP) { cval[pos] = x; cidx[pos] = i4*4 + c; }
                }
            }
        }
    };
    {
        int i = tid;
        for (; i + 5*256 < n4; i += 6*256) {
            float4 v0 = cls4[i];
            float4 v1 = cls4[i + 256];
            float4 v2 = cls4[i + 2*256];
            float4 v3 = cls4[i + 3*256];
            float4 v4 = cls4[i + 4*256];
            float4 v5 = cls4[i + 5*256];
            proc(v0, i); proc(v1, i + 256); proc(v2, i + 2*256);
            proc(v3, i + 3*256); proc(v4, i + 4*256); proc(v5, i + 5*256);
        }
        for (; i < n4; i += 256) proc(cls4[i], i);
    }
    __syncthreads();

    const bool cacheOK = (s_ccnt <= CACHE_CAP);
    const int  ccnt    = s_ccnt < CACHE_CAP ? s_ccnt : CACHE_CAP;

    // warp-based suffix sums: thread owns 4 buckets; 'above' = suffix strictly
    // after this thread's buckets.
    int s4, above;
    {
        int base = tid * 4;
        s4 = hist[base] + hist[base+1] + hist[base+2] + hist[base+3];
        int v = s4;
        #pragma unroll
        for (int off = 1; off < 32; off <<= 1) {
            int t2 = __shfl_down_sync(0xFFFFFFFFu, v, off);
            if (lane + off < 32) v += t2;
        }
        if (lane == 0) wtot[wid] = v;
        __syncthreads();
        int tail = 0;
        for (int ww = wid + 1; ww < 8; ww++) tail += wtot[ww];
        above = (v - s4) + tail;
    }

    // decode + store helper
    auto decode_store = [&](float x, int jrel) {
        int j = j0 + jrel;
        int a = j / HW;
        int rem = j - a*HW;
        const float* bp = boxp0 + ((size_t)(b*AANCH + a) * 4) * HW + rem;
        float d0 = bp[0], d1 = bp[HW], d2 = bp[2*HW], d3 = bp[3*HW];
        float4 an = ((const float4*)anc)[j];
        float w = an.z - an.x, h = an.w - an.y;
        float cx = an.x + 0.5f*w, cy = an.y + 0.5f*h;
        d0 = fminf(fmaxf(d0, -2.0f), 2.0f);
        d1 = fminf(fmaxf(d1, -2.0f), 2.0f);
        d2 = fminf(fmaxf(d2, -2.0f), 2.0f);
        d3 = fminf(fmaxf(d3, -2.0f), 2.0f);
        float px = cx + d0*w, py = cy + d1*h;
        float pw = w * expf(d2), ph = h * expf(d3);
        float x1 = fminf(fmaxf(px - 0.5f*pw, 0.0f), 1024.0f);
        float y1 = fminf(fmaxf(py - 0.5f*ph, 0.0f), 1024.0f);
        float x2 = fminf(fmaxf(px + 0.5f*pw, 0.0f), 1024.0f);
        float y2 = fminf(fmaxf(py + 0.5f*ph, 0.0f), 1024.0f);
        float bw = x2 - x1, bh = y2 - y1;
        if (bw > 1.0f && bh > 1.0f && bw < 2000.0f && bh < 2000.0f) {
            int pos = atomicAdd(&s_cnt, 1);
            if (pos < CAP) {
                int g = pid*CAP + pos;
                g_sc[g] = x;
                g_ix[g] = j;
                g_bx[g] = make_float4(x1, y1, x2, y2);
            }
        }
    };

    int curCut = NB;
    int rawTarget = RAW_TARGET0;
    while (true) {
        if (tid == 0) s_cut = 0;
        __syncthreads();
        // newCut = largest bucket c < curCut with suffix(c) >= rawTarget, else 0
        {
            int base = tid * 4;
            int cum = above;
            for (int k = 3; k >= 0; k--) {
                cum += hist[base + k];
                int c = base + k;
                if (cum >= rawTarget && c < curCut) { atomicMax(&s_cut, c); break; }
            }
        }
        __syncthreads();
        int newCut = s_cut;

        if (cacheOK && newCut >= flBK) {
            // collect band [newCut, curCut) from smem cache
            for (int t = tid; t < ccnt; t += 256) {
                float x = cval[t];
                int bk = (int)(x * LOGIT_SCALE);
                bk = bk > NB-1 ? NB-1 : bk;
                if (bk >= newCut && bk < curCut) decode_store(x, cidx[t]);
            }
        } else {
            // fallback: rescan global cls for the band (exact)
            for (int i = tid; i < n4; i += 256) {
                float4 v = cls4[i];
                float xs[4] = {v.x, v.y, v.z, v.w};
                #pragma unroll
                for (int c4 = 0; c4 < 4; c4++) {
                    float x = xs[c4];
                    if (x > 0.0f) {
                        int bk = (int)(x * LOGIT_SCALE);
                        bk = bk > NB-1 ? NB-1 : bk;
                        if (bk >= newCut && bk < curCut) decode_store(x, i*4 + c4);
                    }
                }
            }
        }
        __syncthreads();
        int cnt = s_cnt;
        curCut = newCut;
        if (cnt >= KPRE || curCut == 0) break;
        rawTarget += (KPRE - cnt) + 32;   // valid shortfall -> extend band
        __syncthreads();
    }
    if (tid == 0) g_cnt[pid] = (s_cnt < CAP) ? s_cnt : CAP;
}

// ---------------------------------------------------------------------------
// Kernel B: per image-level merge -> exact top-300 (sorted) -> NMS -> output.
// Sort key packs (score bits desc | anchor idx asc | slot) in 64 bits, so the
// lax.top_k index tiebreak is preserved with no separate payload.
// ---------------------------------------------------------------------------
__global__ __launch_bounds__(512) void kernelB(float* out, int out_size) {
    const int img = blockIdx.x;
    const int b   = img >> 2;
    const int lvl = img & 3;
    const int partOffA[4] = {0, 8, 10, 11};
    const int partCntA[4] = {8, 2, 1, 1};
    const int p0 = b*PPI + partOffA[lvl];
    const int np = partCntA[lvl];
    const int tid  = threadIdx.x;
    const int wid  = tid >> 5;
    const int lane = tid & 31;

    const bool validAsFloat = (out_size >= 3840);
    unsigned char* validB = (unsigned char*)out + 3200u * 4u;
    const int slot0 = b*40 + lvl*10;

    // zero this block's output region (d_out is poisoned)
    {
        int base5 = b*200 + lvl*50;
        if (tid < 50) out[base5 + tid] = 0.0f;
        if (tid >= 64 && tid < 74) {
            int k = tid - 64;
            if (validAsFloat) out[3200 + slot0 + k] = 0.0f;
            else              validB[slot0 + k] = 0;
        }
    }

    __shared__ int hist[NB];
    __shared__ float s_val[8*CAP];      // staged scores, CAP-strided per part
    __shared__ int wtot[16];
    __shared__ int s_cut, s_scnt;
    __shared__ unsigned long long sKey[SEL];
    __shared__ float sh_x1[KPRE], sh_y1[KPRE], sh_x2[KPRE], sh_y2[KPRE];
    __shared__ float sh_area[KPRE], sh_logit[KPRE];
    __shared__ unsigned sh_keepw[(KPRE+31)/32];
    __shared__ int s_next, s_nk;
    __shared__ int s_pc[8];

    for (int i = tid; i < NB; i += 512) hist[i] = 0;
    if (tid < np) s_pc[tid] = g_cnt[p0 + tid];
    if (tid == 0) { s_scnt = 0; s_nk = 0; s_cut = 0; }
    __syncthreads();

    // stage scores to smem + histogram (single global pass over g_sc)
    for (int k = 0; k < np; k++) {
        int cnt = s_pc[k];
        int base = (p0 + k) * CAP;
        for (int i = tid; i < cnt; i += 512) {
            float x = g_sc[base + i];
            s_val[k*CAP + i] = x;
            int bk = (int)(x * LOGIT_SCALE); bk = bk > NB-1 ? NB-1 : bk;
            atomicAdd(&hist[bk], 1);
        }
    }
    __syncthreads();

    // warp-based suffix scan over 1024 buckets (2 per thread) + cut search
    {
        int base = tid * 2;
        int s2 = hist[base] + hist[base+1];
        int v = s2;
        #pragma unroll
        for (int off = 1; off < 32; off <<= 1) {
            int t2 = __shfl_down_sync(0xFFFFFFFFu, v, off);
            if (lane + off < 32) v += t2;
        }
        if (lane == 0) wtot[wid] = v;
        __syncthreads();
        int tail = 0;
        for (int ww = wid + 1; ww < 16; ww++) tail += wtot[ww];
        int cum = (v - s2) + tail;
        for (int k = 1; k >= 0; k--) {
            cum += hist[base + k];
            if (cum >= KPRE) { atomicMax(&s_cut, base + k); break; }
        }
    }
    __syncthreads();
    int cut = s_cut;

    // collect superset of top-300: 64-bit key = score | ~ancidx | relslot
    for (int k = 0; k < np; k++) {
        int cnt = s_pc[k];
        for (int i = tid; i < cnt; i += 512) {
            int rel = k*CAP + i;
            float x = s_val[rel];
            int bk = (int)(x * LOGIT_SCALE); bk = bk > NB-1 ? NB-1 : bk;
            if (bk >= cut) {
                int pos = atomicAdd(&s_scnt, 1);
                if (pos < SEL) {
                    unsigned j = (unsigned)g_ix[p0*CAP + rel];
                    unsigned lo = ((262143u - j) << 13) | (unsigned)rel;
                    sKey[pos] = ((unsigned long long)__float_as_uint(x) << 32)
                              | (unsigned long long)lo;
                }
            }
        }
    }
    __syncthreads();
    int scnt = s_scnt < SEL ? s_scnt : SEL;
    for (int i = scnt + tid; i < SEL; i += 512) sKey[i] = 0ull;
    __syncthreads();

    // bitonic sort (descending) 512 elems: register-resident key; warp-local
    // phases via shfl_xor (2x32-bit), cross-warp phases via shared + 2 syncs.
    {
        unsigned long long key = sKey[tid];
        __syncthreads();
        #pragma unroll
        for (int k = 2; k <= SEL; k <<= 1) {
            bool segDesc = ((tid & k) == 0);
            #pragma unroll
            for (int j = k >> 1; j > 0; j >>= 1) {
                unsigned long long okey;
                if (j >= 32) {
                    sKey[tid] = key;
                    __syncthreads();
                    okey = sKey[tid ^ j];
                    __syncthreads();
                } else {
                    unsigned hi = __shfl_xor_sync(0xFFFFFFFFu, (unsigned)(key >> 32), j);
                    unsigned lo = __shfl_xor_sync(0xFFFFFFFFu, (unsigned)key, j);
                    okey = ((unsigned long long)hi << 32) | lo;
                }
                bool keepMax = (((tid & j) == 0) == segDesc);
                bool takeOther = keepMax ? (okey > key) : (okey < key);
                if (takeOther) key = okey;
            }
        }
        sKey[tid] = key;
        __syncthreads();
    }

    const int m = scnt < KPRE ? scnt : KPRE;
    for (int i = tid; i < m; i += 512) {
        unsigned long long key = sKey[i];
        int rel = (int)(key & 0x1FFFu);
        float4 bb = g_bx[p0*CAP + rel];
        sh_x1[i] = bb.x; sh_y1[i] = bb.y; sh_x2[i] = bb.z; sh_y2[i] = bb.w;
        sh_area[i] = (bb.z - bb.x) * (bb.w - bb.y);
        sh_logit[i] = __uint_as_float((unsigned)(key >> 32));
    }
    if (tid < (KPRE+31)/32) {
        int lo = tid * 32;
        unsigned w;
        if (m >= lo + 32) w = 0xFFFFFFFFu;
        else if (m > lo)  w = (1u << (m - lo)) - 1u;
        else              w = 0u;
        sh_keepw[tid] = w;
    }
    __syncthreads();

    // greedy NMS, one round per KEPT box (<= 10): find lowest surviving
    // candidate, emit, suppress in parallel. Exact: later keeps cannot alter
    // the first-10 prefix.
    for (int round = 0; round <= KOUT; round++) {
        if (tid < 32) {
            unsigned v = (tid < 10) ? sh_keepw[tid] : 0u;
            unsigned nz = __ballot_sync(0xFFFFFFFFu, v != 0u);
            int w = __ffs(nz) - 1;
            unsigned vw = __shfl_sync(0xFFFFFFFFu, v, (w < 0) ? 0 : w);
            if (tid == 0) s_next = nz ? (w*32 + __ffs(vw) - 1) : -1;
        }
        __syncthreads();
        int i = s_next;
        if (i < 0 || s_nk >= KOUT) break;

        float bx1 = sh_x1[i], by1 = sh_y1[i], bx2 = sh_x2[i], by2 = sh_y2[i];
        float ba = sh_area[i];

        if (tid == 0) {
            int nk = s_nk;
            float sc = 1.0f / (1.0f + expf(-sh_logit[i]));
            int s5 = b*200 + (lvl*10 + nk)*5;
            out[s5+0] = bx1; out[s5+1] = by1;
            out[s5+2] = bx2; out[s5+3] = by2;
            out[s5+4] = sc;
            if (validAsFloat) out[3200 + slot0 + nk] = 1.0f;
            else              validB[slot0 + nk] = 1;
            s_nk = nk + 1;
            atomicAnd(&sh_keepw[i >> 5], ~(1u << (i & 31)));
        }
        int j = tid;
        if (j > i && j < m && ((sh_keepw[j >> 5] >> (j & 31)) & 1u)) {
            float ix1 = fmaxf(bx1, sh_x1[j]);
            float iy1 = fmaxf(by1, sh_y1[j]);
            float ix2 = fminf(bx2, sh_x2[j]);
            float iy2 = fminf(by2, sh_y2[j]);
            float iw = fmaxf(ix2 - ix1, 0.0f);
            float ih = fmaxf(iy2 - iy1, 0.0f);
            float inter = iw * ih;
            float iou = inter / (ba + sh_area[j] - inter + 1e-9f);
            if (iou > 0.3f) atomicAnd(&sh_keepw[j >> 5], ~(1u << (j & 31)));
        }
        __syncthreads();
    }
}

// ---------------------------------------------------------------------------
extern "C" void kernel_launch(void* const* d_in, const int* in_sizes, int n_in,
                              void* d_out, int out_size) {
    Ptrs P;
    if (n_in >= 2 && in_sizes[0] == 2359296 && in_sizes[1] == 9437184) {
        for (int l = 0; l < 4; l++) {
            P.cls[l] = (const float*)d_in[3*l + 0];
            P.box[l] = (const float*)d_in[3*l + 1];
            P.anc[l] = (const float*)d_in[3*l + 2];
        }
    } else if (n_in >= 1 && in_sizes[0] == 2359296) {
        for (int l = 0; l < 4; l++) {
            P.cls[l] = (const float*)d_in[l];
            P.box[l] = (const float*)d_in[4 + l];
            P.anc[l] = (const float*)d_in[8 + l];
        }
    } else {
        for (int l = 0; l < 4; l++) {
            P.anc[l] = (const float*)d_in[l];
            P.box[l] = (const float*)d_in[4 + l];
            P.cls[l] = (const float*)d_in[8 + l];
        }
    }
    kernelA<<<NPARTS, 256>>>(P);
    kernelB<<<64, 512>>>((float*)d_out, out_size);
}

// round 6
// speedup vs baseline: 1.7784x; 1.1128x over previous
#include <cuda_runtime.h>
#include <math.h>

#define NB        1024
#define LSCALE    128.0f
#define KPRE      300
#define KOUT      10
#define SEGSZ     384          // 8 segments x 384 = 3072 cache entries
#define CANDCAP   640
#define SORTN     1024
#define RAW_T0    420          // first-band overshoot (valid-rate slack)

struct Ptrs {
    const float* cls[4];
    const float* box[4];
    const float* anc[4];
};

// One CTA per (batch, level): stream cls -> floored histogram + segmented
// smem cache -> exact top-K cut -> decode band -> 1024-wide bitonic sort
// (key = score|~ancidx|slot, preserves lax.top_k tie order) -> register NMS.
__global__ __launch_bounds__(1024) void detect_kernel(Ptrs P, float* out, int out_size) {
    const int img = blockIdx.x;
    const int b   = img >> 2;
    const int lvl = img & 3;
    const int HW  = 16384 >> (2*lvl);          // 16384,4096,1024,256
    const int N   = 9 * HW;
    // cache floor bucket per level (expected above-floor counts ~2k-2.5k << 3072)
    const int flBK = (lvl==0) ? 281 : (lvl==1) ? 192 : (lvl==2) ? 128 : 0;
    const float* cls  = P.cls[lvl] + (size_t)b * N;
    const float* boxp = P.box[lvl];
    const float* anc  = P.anc[lvl];
    const int tid = threadIdx.x, wid = tid >> 5, lane = tid & 31;

    __shared__ int   hist[NB];
    __shared__ float cval[8*SEGSZ];
    __shared__ int   cidx[8*SEGSZ];
    __shared__ unsigned long long candKey[SORTN];
    __shared__ float4 candBox[CANDCAP];
    __shared__ int   wtot[32];
    __shared__ int   s_seg[8];
    __shared__ int   s_cnt, s_cut, s_next, s_nk;
    __shared__ unsigned keepw[10];

    const bool vF = (out_size >= 3840);
    unsigned char* vB = (unsigned char*)out + 12800;
    const int slot0 = b*40 + lvl*10;

    // zero this CTA's output region (d_out is poisoned)
    {
        int base5 = b*200 + lvl*50;
        if (tid < 50) out[base5 + tid] = 0.0f;
        if (tid >= 64 && tid < 74) {
            int k = tid - 64;
            if (vF) out[3200 + slot0 + k] = 0.0f;
            else    vB[slot0 + k] = 0;
        }
    }
    hist[tid] = 0;
    if (tid < 8) s_seg[tid] = 0;
    if (tid == 0) s_cnt = 0;
    __syncthreads();

    const int n4 = N >> 2;
    const float4* cls4 = (const float4*)cls;
    const int seg = wid & 7;

    // pass 1: stream cls; histogram + cache only entries above the floor.
    auto proc = [&](float4 v, int i4) {
        float xs[4] = {v.x, v.y, v.z, v.w};
        #pragma unroll
        for (int c = 0; c < 4; c++) {
            float x = xs[c];
            if (x > 0.0f) {
                int bk = (int)(x * LSCALE); bk = bk > NB-1 ? NB-1 : bk;
                if (bk >= flBK) {
                    atomicAdd(&hist[bk], 1);
                    int p = atomicAdd(&s_seg[seg], 1);
                    if (p < SEGSZ) { cval[seg*SEGSZ + p] = x; cidx[seg*SEGSZ + p] = i4*4 + c; }
                }
            }
        }
    };
    {
        int i = tid;
        for (; i + 7*1024 < n4; i += 8*1024) {
            float4 v0 = cls4[i];          float4 v1 = cls4[i + 1024];
            float4 v2 = cls4[i + 2048];   float4 v3 = cls4[i + 3072];
            float4 v4 = cls4[i + 4096];   float4 v5 = cls4[i + 5120];
            float4 v6 = cls4[i + 6144];   float4 v7 = cls4[i + 7168];
            proc(v0, i);        proc(v1, i + 1024);
            proc(v2, i + 2048); proc(v3, i + 3072);
            proc(v4, i + 4096); proc(v5, i + 5120);
            proc(v6, i + 6144); proc(v7, i + 7168);
        }
        for (; i < n4; i += 1024) proc(cls4[i], i);
    }
    __syncthreads();

    bool cacheOK = true;
    #pragma unroll
    for (int s = 0; s < 8; s++) cacheOK = cacheOK && (s_seg[s] <= SEGSZ);

    // per-thread suffix count strictly after this thread's bucket
    auto computeAbove = [&]() -> int {
        __syncthreads();
        int h = hist[tid];
        int v = h;
        #pragma unroll
        for (int off = 1; off < 32; off <<= 1) {
            int t2 = __shfl_down_sync(0xFFFFFFFFu, v, off);
            if (lane + off < 32) v += t2;
        }
        if (lane == 0) wtot[wid] = v;
        __syncthreads();
        int tail = 0;
        for (int w = wid + 1; w < 32; w++) tail += wtot[w];
        return (v - h) + tail;
    };

    auto decode_store = [&](float x, int j) {
        int a = j / HW;
        int rem = j - a*HW;
        const float* bp = boxp + ((size_t)(b*9 + a) * 4) * HW + rem;
        float d0 = bp[0], d1 = bp[HW], d2 = bp[2*HW], d3 = bp[3*HW];
        float4 an = ((const float4*)anc)[j];
        float w = an.z - an.x, h = an.w - an.y;
        float cx = an.x + 0.5f*w, cy = an.y + 0.5f*h;
        d0 = fminf(fmaxf(d0, -2.0f), 2.0f);
        d1 = fminf(fmaxf(d1, -2.0f), 2.0f);
        d2 = fminf(fmaxf(d2, -2.0f), 2.0f);
        d3 = fminf(fmaxf(d3, -2.0f), 2.0f);
        float px = cx + d0*w, py = cy + d1*h;
        float pw = w * expf(d2), ph = h * expf(d3);
        float x1 = fminf(fmaxf(px - 0.5f*pw, 0.0f), 1024.0f);
        float y1 = fminf(fmaxf(py - 0.5f*ph, 0.0f), 1024.0f);
        float x2 = fminf(fmaxf(px + 0.5f*pw, 0.0f), 1024.0f);
        float y2 = fminf(fmaxf(py + 0.5f*ph, 0.0f), 1024.0f);
        float bw = x2 - x1, bh = y2 - y1;
        if (bw > 1.0f && bh > 1.0f && bw < 2000.0f && bh < 2000.0f) {
            int pos = atomicAdd(&s_cnt, 1);
            if (pos < CANDCAP) {
                unsigned lo = ((262143u - (unsigned)j) << 10) | (unsigned)pos;
                candKey[pos] = ((unsigned long long)__float_as_uint(x) << 32) | lo;
                candBox[pos] = make_float4(x1, y1, x2, y2);
            }
        }
    };

    int above = computeAbove();
    bool histFull = (flBK == 0);
    int curCut = NB;
    int rawTarget = RAW_T0;
    while (true) {
        if (tid == 0) s_cut = 0;
        __syncthreads();
        // crossing bucket: unique tid with suffix>=target but strictly-after<target
        {
            int cum = above + hist[tid];
            if (tid < curCut && cum >= rawTarget && above < rawTarget) s_cut = tid;
        }
        __syncthreads();
        int newCut = s_cut;

        if (!histFull && newCut < flBK) {
            // cold path: extend histogram below the floor (exactness guard)
            for (int i = tid; i < n4; i += 1024) {
                float4 v = cls4[i];
                float xs[4] = {v.x, v.y, v.z, v.w};
                for (int c = 0; c < 4; c++) {
                    float x = xs[c];
                    if (x > 0.0f) {
                        int bk = (int)(x * LSCALE); bk = bk > NB-1 ? NB-1 : bk;
                        if (bk < flBK) atomicAdd(&hist[bk], 1);
                    }
                }
            }
            histFull = true;
            above = computeAbove();
            continue;
        }

        if (cacheOK && newCut >= flBK) {
            // collect band [newCut, curCut) from smem cache segments
            for (int t = tid; t < 8*SEGSZ; t += 1024) {
                int sg = t / SEGSZ, o = t - sg*SEGSZ;
                if (o < s_seg[sg]) {
                    float x = cval[t];
                    int bk = (int)(x * LSCALE); bk = bk > NB-1 ? NB-1 : bk;
                    if (bk >= newCut && bk < curCut) decode_store(x, cidx[t]);
                }
            }
        } else {
            // exact fallback: rescan global for the band
            for (int i = tid; i < n4; i += 1024) {
                float4 v = cls4[i];
                float xs[4] = {v.x, v.y, v.z, v.w};
                for (int c = 0; c < 4; c++) {
                    float x = xs[c];
                    if (x > 0.0f) {
                        int bk = (int)(x * LSCALE); bk = bk > NB-1 ? NB-1 : bk;
                        if (bk >= newCut && bk < curCut) decode_store(x, i*4 + c);
                    }
                }
            }
        }
        __syncthreads();
        int cnt = s_cnt;
        curCut = newCut;
        if (cnt >= KPRE || curCut == 0) break;
        rawTarget += (KPRE - cnt) + 32;   // valid shortfall -> extend band
        __syncthreads();
    }

    int scnt = s_cnt < CANDCAP ? s_cnt : CANDCAP;
    if (tid >= scnt) candKey[tid] = 0ull;
    __syncthreads();

    // bitonic sort, descending, 1024 elems / 1024 threads (uniform, no guards)
    {
        unsigned long long key = candKey[tid];
        __syncthreads();
        #pragma unroll
        for (int k = 2; k <= SORTN; k <<= 1) {
            bool segDesc = ((tid & k) == 0);
            #pragma unroll
            for (int j = k >> 1; j > 0; j >>= 1) {
                unsigned long long okey;
                if (j >= 32) {
                    candKey[tid] = key;
                    __syncthreads();
                    okey = candKey[tid ^ j];
                    __syncthreads();
                } else {
                    unsigned hi = __shfl_xor_sync(0xFFFFFFFFu, (unsigned)(key >> 32), j);
                    unsigned lo = __shfl_xor_sync(0xFFFFFFFFu, (unsigned)key, j);
                    okey = ((unsigned long long)hi << 32) | lo;
                }
                bool keepMax = (((tid & j) == 0) == segDesc);
                bool take = keepMax ? (okey > key) : (okey < key);
                if (take) key = okey;
            }
        }
        candKey[tid] = key;
        __syncthreads();
    }

    // NMS: each thread holds its candidate's box in registers
    const int m = scnt < KPRE ? scnt : KPRE;
    float mx1 = 0, my1 = 0, mx2 = 0, my2 = 0, mar = 0;
    if (tid < m) {
        unsigned long long kk = candKey[tid];
        float4 bb = candBox[(int)(kk & 1023u)];
        mx1 = bb.x; my1 = bb.y; mx2 = bb.z; my2 = bb.w;
        mar = (bb.z - bb.x) * (bb.w - bb.y);
    }
    if (tid < 10) {
        int lo = tid * 32;
        unsigned w;
        if (m >= lo + 32) w = 0xFFFFFFFFu;
        else if (m > lo)  w = (1u << (m - lo)) - 1u;
        else              w = 0u;
        keepw[tid] = w;
    }
    if (tid == 0) s_nk = 0;
    __syncthreads();

    // one round per kept box (<=10); exact: later keeps cannot alter prefix
    for (int round = 0; round <= KOUT; round++) {
        if (tid < 32) {
            unsigned v = (tid < 10) ? keepw[tid] : 0u;
            unsigned nz = __ballot_sync(0xFFFFFFFFu, v != 0u);
            int w = __ffs(nz) - 1;
            unsigned vw = __shfl_sync(0xFFFFFFFFu, v, (w < 0) ? 0 : w);
            if (tid == 0) s_next = nz ? (w*32 + __ffs(vw) - 1) : -1;
        }
        __syncthreads();
        int i = s_next;
        if (i < 0 || s_nk >= KOUT) break;

        unsigned long long ki = candKey[i];            // broadcast
        float4 bi = candBox[(int)(ki & 1023u)];        // broadcast
        float ba = (bi.z - bi.x) * (bi.w - bi.y);

        if (tid == 0) {
            int nk = s_nk;
            float logit = __uint_as_float((unsigned)(ki >> 32));
            float sc = 1.0f / (1.0f + expf(-logit));
            int s5 = b*200 + (lvl*10 + nk)*5;
            out[s5+0] = bi.x; out[s5+1] = bi.y;
            out[s5+2] = bi.z; out[s5+3] = bi.w;
            out[s5+4] = sc;
            if (vF) out[3200 + slot0 + nk] = 1.0f;
            else    vB[slot0 + nk] = 1;
            s_nk = nk + 1;
            atomicAnd(&keepw[i >> 5], ~(1u << (i & 31)));
        }
        if (tid > i && tid < m && ((keepw[tid >> 5] >> (tid & 31)) & 1u)) {
            float ix1 = fmaxf(bi.x, mx1), iy1 = fmaxf(bi.y, my1);
            float ix2 = fminf(bi.z, mx2), iy2 = fminf(bi.w, my2);
            float iw = fmaxf(ix2 - ix1, 0.0f), ih = fmaxf(iy2 - iy1, 0.0f);
            float inter = iw * ih;
            float iou = inter / (ba + mar - inter + 1e-9f);
            if (iou > 0.3f) atomicAnd(&keepw[tid >> 5], ~(1u << (tid & 31)));
        }
        __syncthreads();
    }
}

// ---------------------------------------------------------------------------
extern "C" void kernel_launch(void* const* d_in, const int* in_sizes, int n_in,
                              void* d_out, int out_size) {
    Ptrs P;
    if (n_in >= 2 && in_sizes[0] == 2359296 && in_sizes[1] == 9437184) {
        for (int l = 0; l < 4; l++) {
            P.cls[l] = (const float*)d_in[3*l + 0];
            P.box[l] = (const float*)d_in[3*l + 1];
            P.anc[l] = (const float*)d_in[3*l + 2];
        }
    } else if (n_in >= 1 && in_sizes[0] == 2359296) {
        for (int l = 0; l < 4; l++) {
            P.cls[l] = (const float*)d_in[l];
            P.box[l] = (const float*)d_in[4 + l];
            P.anc[l] = (const float*)d_in[8 + l];
        }
    } else {
        for (int l = 0; l < 4; l++) {
            P.anc[l] = (const float*)d_in[l];
            P.box[l] = (const float*)d_in[4 + l];
            P.cls[l] = (const float*)d_in[8 + l];
        }
    }
    detect_kernel<<<64, 1024>>>(P, (float*)d_out, out_size);
}